// round 11
// baseline (speedup 1.0000x reference)
#include <cuda_runtime.h>
#include <math.h>

#define BATCH   16
#define DMODEL  512
#define DSTATE  64
#define LEN     4096

// ---------------- scratch (device globals: no allocations allowed) ----------
__device__ __align__(16) float g_zr[DMODEL*DSTATE];
__device__ __align__(16) float g_zi[DMODEL*DSTATE];
__device__ __align__(16) float g_wr[DMODEL*DSTATE];
__device__ __align__(16) float g_wi[DMODEL*DSTATE];
__device__ __align__(16) float g_w2r[DMODEL*DSTATE];
__device__ __align__(16) float g_w2i[DMODEL*DSTATE];
__device__ __align__(16) float g_gelu[(size_t)BATCH*DMODEL*LEN];   // 128 MB
__device__ __align__(16) float g_pooled[BATCH*DMODEL];
// W pre-packed into mma fragment order (tf32 bits): [rblk8][kt32][h2][mf8][lane32][reg4]
__device__ __align__(16) unsigned int g_Wp[8*32*2048];

__device__ __forceinline__ unsigned int f2tf32(float x) {
    unsigned int r;
    asm("cvt.rna.tf32.f32 %0, %1;" : "=r"(r) : "f"(x));
    return r;
}

// ---------------- packed f32x2 helpers (sm_103a FFMA2 path) -----------------
typedef unsigned long long f32x2;
__device__ __forceinline__ f32x2 pk2(float lo, float hi) {
    f32x2 r; asm("mov.b64 %0, {%1, %2};" : "=l"(r) : "f"(lo), "f"(hi)); return r;
}
__device__ __forceinline__ void upk2(float& lo, float& hi, f32x2 v) {
    asm("mov.b64 {%0, %1}, %2;" : "=f"(lo), "=f"(hi) : "l"(v));
}
__device__ __forceinline__ f32x2 fma2(f32x2 a, f32x2 b, f32x2 c) {
    f32x2 d; asm("fma.rn.f32x2 %0, %1, %2, %3;" : "=l"(d) : "l"(a), "l"(b), "l"(c)); return d;
}
__device__ __forceinline__ f32x2 mul2(f32x2 a, f32x2 b) {
    f32x2 d; asm("mul.rn.f32x2 %0, %1, %2;" : "=l"(d) : "l"(a), "l"(b)); return d;
}
__device__ __forceinline__ f32x2 add2(f32x2 a, f32x2 b) {
    f32x2 d; asm("add.rn.f32x2 %0, %1, %2;" : "=l"(d) : "l"(a), "l"(b)); return d;
}

// ---------------- kernel 1: SSM constants (fp64 for phase accuracy) ---------
__global__ void k_params(const float* __restrict__ log_dt,
                         const float* __restrict__ log_A_real,
                         const float* __restrict__ A_imag,
                         const float* __restrict__ B_re,
                         const float* __restrict__ B_im,
                         const float* __restrict__ C_re,
                         const float* __restrict__ C_im) {
    int i = blockIdx.x * blockDim.x + threadIdx.x;
    if (i >= DMODEL * DSTATE) return;
    int d = i / DSTATE;
    double dt   = exp((double)log_dt[d]);
    double Ar   = -exp((double)log_A_real[i]);
    double Ai   = (double)A_imag[i];
    double dtAr = Ar * dt, dtAi = Ai * dt;
    double er = exp(dtAr);
    double zr = er * cos(dtAi), zi = er * sin(dtAi);
    double den  = Ar * Ar + Ai * Ai;
    double numr = zr - 1.0, numi = zi;
    double qr = (numr * Ar + numi * Ai) / den;
    double qi = (numi * Ar - numr * Ai) / den;
    double Br = (double)B_re[i], Bi = (double)B_im[i];
    double bbr = qr * Br - qi * Bi, bbi = qr * Bi + qi * Br;
    double Cr = (double)C_re[i], Ci = (double)C_im[i];
    double wr = Cr * bbr - Ci * bbi, wi = Cr * bbi + Ci * bbr;
    double eL = exp((double)LEN * dtAr);
    double ph = (double)LEN * dtAi;
    double zLr = eL * cos(ph), zLi = eL * sin(ph);
    double w2r = -(wr * zLr - wi * zLi);
    double w2i = -(wr * zLi + wi * zLr);
    g_zr[i] = (float)zr;  g_zi[i] = (float)zi;
    g_wr[i] = (float)wr;  g_wi[i] = (float)wi;
    g_w2r[i] = (float)w2r; g_w2i[i] = (float)w2i;
}

// ---------------- kernel 1b: pack W into tf32 mma fragment order ------------
__global__ void k_packW(const float* __restrict__ W) {
    int flat = blockIdx.x * blockDim.x + threadIdx.x;   // 524288 total
    int reg  = flat & 3;
    int lane = (flat >> 2) & 31;
    int mf8  = (flat >> 7) & 7;
    int h    = (flat >> 10) & 1;
    int kt   = (flat >> 11) & 31;
    int rb   = flat >> 16;
    int m = mf8 * 16 + (lane >> 2) + 8 * (reg & 1);
    int k = kt * 16 + h * 8 + (lane & 3) + 4 * (reg >> 1);
    int wrow = (m < 64) ? rb * 64 + m : 448 + rb * 64 + m;
    g_Wp[flat] = f2tf32(W[wrow * 512 + k]);
}

// ---------------- kernel 2: zero pooled accumulator -------------------------
__global__ void k_zero() {
    int i = blockIdx.x * blockDim.x + threadIdx.x;
    if (i < BATCH * DMODEL) g_pooled[i] = 0.0f;
}

// ---------------- kernel 3: packed Goertzel scan + skip + GELU --------------
// One warp per (b,d); 2 states per lane packed into f32x2 (n=lane, n=lane+32).
// Pass A: s(x) = u[x] + p s(x+1) + q s(x+2); H0 = s(0) - conj(z) s(1).
// Pass B: R(x) = p R(x+1) + q R(x+2) + c1 u[x+1] + c0 u[x+2],
//         c1 = w2r, c0 = -Re(conj(z) w2), primed from E(L-1) = w*H0.
#define ROWW 68   // floats per smem row (32 float2 + pad), 272B = 17*16B aligned

__global__ __launch_bounds__(128) void k_scan(const float* __restrict__ u,
                                              const float* __restrict__ Dp) {
    __shared__ __align__(16) float sbuf[4][32 * ROWW];

    int wid  = threadIdx.x >> 5;
    int lane = threadIdx.x & 31;
    int bd = blockIdx.x * 4 + wid;
    int d  = bd & (DMODEL - 1);
    const float* ub = u + (size_t)bd * LEN;
    float* gb = g_gelu + (size_t)bd * LEN;
    float* sbw = sbuf[wid];

    int dn0 = d * DSTATE + lane;
    int dn1 = dn0 + 32;
    float zra = g_zr[dn0], zia = g_zi[dn0];
    float zrb = g_zr[dn1], zib = g_zi[dn1];
    float pa = 2.0f * zra, qa = -fmaf(zra, zra, zia * zia);
    float pb = 2.0f * zrb, qb = -fmaf(zrb, zrb, zib * zib);
    float Dd = Dp[d];

    f32x2 pv = pk2(pa, pb), qv = pk2(qa, qb);

    // ---- pass A: packed Goertzel (2 FFMA2/step for both states) ----
    f32x2 s1v = 0ull, s2v = 0ull;
    for (int x0 = LEN - 32; x0 >= 0; x0 -= 32) {
        float ul = ub[x0 + lane];
        #pragma unroll
        for (int t = 31; t >= 0; --t) {
            float uu = __shfl_sync(0xffffffffu, ul, t);
            f32x2 uv = pk2(uu, uu);
            f32x2 nv = fma2(pv, s1v, fma2(qv, s2v, uv));
            s2v = s1v; s1v = nv;
        }
    }
    float s1a, s1b, s2a, s2b;
    upk2(s1a, s1b, s1v);
    upk2(s2a, s2b, s2v);

    // ---- boundary priming (complex, once, scalar) ----
    float uL1 = __ldg(ub + LEN - 1);
    float c1a, c0a, r1a, r2a, c1b, c0b, r1b, r2b;
    {
        float wr = g_wr[dn0], wi = g_wi[dn0];
        float w2r = g_w2r[dn0], w2i = g_w2i[dn0];
        float H0r = fmaf(-zra, s2a, s1a), H0i = zia * s2a;
        float mr = fmaf(wr, H0r, -wi * H0i);
        float mi = fmaf(wr, H0i,  wi * H0r);
        float RL1 = mr;
        float RL2 = fmaf(zra, mr, fmaf(-zia, mi, w2r * uL1));
        c1a = w2r;
        c0a = -fmaf(zra, w2r, zia * w2i);
        float invq = 1.0f / qa;
        r1a = (RL2 - pa * RL1 - c1a * uL1) * invq;   // ghost R(L)
        r2a = (RL1 - pa * r1a) * invq;               // ghost R(L+1)
    }
    {
        float wr = g_wr[dn1], wi = g_wi[dn1];
        float w2r = g_w2r[dn1], w2i = g_w2i[dn1];
        float H0r = fmaf(-zrb, s2b, s1b), H0i = zib * s2b;
        float mr = fmaf(wr, H0r, -wi * H0i);
        float mi = fmaf(wr, H0i,  wi * H0r);
        float RL1 = mr;
        float RL2 = fmaf(zrb, mr, fmaf(-zib, mi, w2r * uL1));
        c1b = w2r;
        c0b = -fmaf(zrb, w2r, zib * w2i);
        float invq = 1.0f / qb;
        r1b = (RL2 - pb * RL1 - c1b * uL1) * invq;
        r2b = (RL1 - pb * r1b) * invq;
    }

    f32x2 c1v = pk2(c1a, c1b), c0v = pk2(c0a, c0b);
    f32x2 r1v = pk2(r1a, r1b), r2v = pk2(r2a, r2b);
    f32x2 u1v = 0ull, u2v = 0ull;                    // ghost u[L], u[L+1]

    // ---- pass B: packed real 2nd-order emission (4 FFMA2/step) ----
    for (int x0 = LEN - 32; x0 >= 0; x0 -= 32) {
        float ul = ub[x0 + lane];
        #pragma unroll
        for (int t = 31; t >= 0; --t) {
            float uu = __shfl_sync(0xffffffffu, ul, t);
            f32x2 uv = pk2(uu, uu);
            f32x2 tv = fma2(c1v, u1v, mul2(c0v, u2v));
            tv = fma2(qv, r2v, tv);
            f32x2 Rv = fma2(pv, r1v, tv);
            *reinterpret_cast<f32x2*>(sbw + t * ROWW + lane * 2) = Rv;  // STS.64 packed
            r2v = r1v; r1v = Rv;
            u2v = u1v; u1v = uv;
        }
        __syncwarp();
        // reduce 64 states = 32 packed pairs in row `lane` (conflict-free LDS.128)
        const ulonglong2* row = reinterpret_cast<const ulonglong2*>(sbw + lane * ROWW);
        f32x2 acc0 = 0ull, acc1 = 0ull;
        #pragma unroll
        for (int k = 0; k < 16; ++k) {
            ulonglong2 v = row[k];
            acc0 = add2(acc0, v.x);
            acc1 = add2(acc1, v.y);
        }
        f32x2 accv = add2(acc0, acc1);
        float alo, ahi;
        upk2(alo, ahi, accv);
        float yv = fmaf(Dd, ul, alo + ahi);
        float gv = 0.5f * yv * (1.0f + erff(yv * 0.7071067811865475f));
        gb[x0 + lane] = gv;
        __syncwarp();
    }
}

// ---------------- kernel 4: tf32 tensor-core GEMM + GLU + mean fused --------
#define SA_STRIDE 2048
#define SB_GRP    66
#define SB_STRIDE (32*SB_GRP)

__device__ __forceinline__ void mma_tf32(float* c, const uint4 a, const uint2 b) {
    asm volatile(
        "mma.sync.aligned.m16n8k8.row.col.f32.tf32.tf32.f32 "
        "{%0,%1,%2,%3}, {%4,%5,%6,%7}, {%8,%9}, {%0,%1,%2,%3};"
        : "+f"(c[0]), "+f"(c[1]), "+f"(c[2]), "+f"(c[3])
        : "r"(a.x), "r"(a.y), "r"(a.z), "r"(a.w), "r"(b.x), "r"(b.y));
}

__global__ __launch_bounds__(256) void k_gemm(const float* __restrict__ bout) {
    __shared__ __align__(16) float sh[8576];
    float* sA = sh;
    float* sB = sh + 2 * SA_STRIDE;

    int tid = threadIdx.x;
    int w = tid >> 5, lane = tid & 31;
    int wm = w & 1, wn = w >> 1;
    int rblk = blockIdx.x;
    int nblk = blockIdx.y;
    int col0 = nblk * 128;
    int b = col0 >> 12;
    const float* yg = g_gelu + (size_t)b * DMODEL * LEN + (col0 & (LEN - 1));
    const unsigned int* Wp = g_Wp + rblk * (32 * 2048);

    float acc[4][4][4];
    #pragma unroll
    for (int i = 0; i < 4; ++i)
        #pragma unroll
        for (int j = 0; j < 4; ++j)
            #pragma unroll
            for (int r = 0; r < 4; ++r) acc[i][j][r] = 0.0f;

    #pragma unroll
    for (int i = 0; i < 2; ++i) {
        int ia = tid + i * 256;
        uint4 va = *reinterpret_cast<const uint4*>(Wp + (size_t)ia * 4);
        *reinterpret_cast<uint4*>(reinterpret_cast<unsigned int*>(sA) + ia * 4) = va;
        int k = ia >> 5, n0 = (ia & 31) << 2;
        float4 vb = *reinterpret_cast<const float4*>(yg + (size_t)k * LEN + n0);
        float v[4] = {vb.x, vb.y, vb.z, vb.w};
        int h = k >> 3, kk = k & 3, reg = (k >> 2) & 1;
        #pragma unroll
        for (int e = 0; e < 4; ++e) {
            int nn = n0 + e;
            int l = ((nn & 7) << 2) | kk;
            sB[(h * 16 + (nn >> 3)) * SB_GRP + l * 2 + reg] = __uint_as_float(f2tf32(v[e]));
        }
    }
    __syncthreads();

    for (int kt = 0; kt < 32; ++kt) {
        int buf = kt & 1;
        bool has = kt < 31;
        uint4 pa[2]; float4 pb[2];
        if (has) {
            #pragma unroll
            for (int i = 0; i < 2; ++i) {
                int ia = tid + i * 256;
                pa[i] = *reinterpret_cast<const uint4*>(Wp + (size_t)(kt + 1) * 2048 + (size_t)ia * 4);
                int k = ia >> 5, n0 = (ia & 31) << 2;
                pb[i] = *reinterpret_cast<const float4*>(yg + (size_t)((kt + 1) * 16 + k) * LEN + n0);
            }
        }
        const float* sAb = sA + buf * SA_STRIDE;
        const float* sBb = sB + buf * SB_STRIDE;
        #pragma unroll
        for (int h = 0; h < 2; ++h) {
            uint4 af[4]; uint2 bf[4];
            #pragma unroll
            for (int mf = 0; mf < 4; ++mf)
                af[mf] = *reinterpret_cast<const uint4*>(sAb + ((h * 8 + wm * 4 + mf) * 128 + lane * 4));
            #pragma unroll
            for (int nf = 0; nf < 4; ++nf)
                bf[nf] = *reinterpret_cast<const uint2*>(sBb + (h * 16 + wn * 4 + nf) * SB_GRP + lane * 2);
            #pragma unroll
            for (int mf = 0; mf < 4; ++mf)
                #pragma unroll
                for (int nf = 0; nf < 4; ++nf)
                    mma_tf32(acc[mf][nf], af[mf], bf[nf]);
        }
        if (has) {
            int nb = buf ^ 1;
            #pragma unroll
            for (int i = 0; i < 2; ++i) {
                int ia = tid + i * 256;
                *reinterpret_cast<uint4*>(reinterpret_cast<unsigned int*>(sA + nb * SA_STRIDE) + ia * 4) = pa[i];
                int k = ia >> 5, n0 = (ia & 31) << 2;
                float v[4] = {pb[i].x, pb[i].y, pb[i].z, pb[i].w};
                int h = k >> 3, kk = k & 3, reg = (k >> 2) & 1;
                float* sBn = sB + nb * SB_STRIDE;
                #pragma unroll
                for (int e = 0; e < 4; ++e) {
                    int nn = n0 + e;
                    int l = ((nn & 7) << 2) | kk;
                    sBn[(h * 16 + (nn >> 3)) * SB_GRP + l * 2 + reg] = __uint_as_float(f2tf32(v[e]));
                }
            }
        }
        __syncthreads();
    }

    float* Sg  = sh;
    float* red = sh + 64 * 129;

    if (wm == 1) {
        #pragma unroll
        for (int mf = 0; mf < 4; ++mf)
            #pragma unroll
            for (int hi = 0; hi < 2; ++hi) {
                int row = mf * 16 + (lane >> 2) + 8 * hi;
                float bo = bout[512 + rblk * 64 + row];
                #pragma unroll
                for (int nf = 0; nf < 4; ++nf)
                    #pragma unroll
                    for (int c01 = 0; c01 < 2; ++c01) {
                        int col = wn * 32 + nf * 8 + ((lane & 3) << 1) + c01;
                        float gv = acc[mf][nf][2 * hi + c01] + bo;
                        Sg[row * 129 + col] = 1.0f / (1.0f + expf(-gv));
                    }
            }
    }
    __syncthreads();
    if (wm == 0) {
        #pragma unroll
        for (int mf = 0; mf < 4; ++mf)
            #pragma unroll
            for (int hi = 0; hi < 2; ++hi) {
                int row = mf * 16 + (lane >> 2) + 8 * hi;
                float bo = bout[rblk * 64 + row];
                float rs = 0.0f;
                #pragma unroll
                for (int nf = 0; nf < 4; ++nf)
                    #pragma unroll
                    for (int c01 = 0; c01 < 2; ++c01) {
                        int col = wn * 32 + nf * 8 + ((lane & 3) << 1) + c01;
                        rs += (acc[mf][nf][2 * hi + c01] + bo) * Sg[row * 129 + col];
                    }
                rs += __shfl_xor_sync(0xffffffffu, rs, 1);
                rs += __shfl_xor_sync(0xffffffffu, rs, 2);
                if ((lane & 3) == 0) red[row * 4 + wn] = rs;
            }
    }
    __syncthreads();
    if (tid < 64) {
        float s = red[tid * 4] + red[tid * 4 + 1] + red[tid * 4 + 2] + red[tid * 4 + 3];
        atomicAdd(&g_pooled[b * DMODEL + rblk * 64 + tid], s);
    }
}

// ---------------- kernel 5: mean scale + decoder ----------------------------
__global__ void k_final(const float* __restrict__ Wd,
                        const float* __restrict__ bd,
                        float* __restrict__ out) {
    int b = blockIdx.x;
    __shared__ float r[256];
    float s = 0.0f;
    for (int c = threadIdx.x; c < DMODEL; c += 256)
        s += Wd[c] * g_pooled[b * DMODEL + c];
    r[threadIdx.x] = s;
    __syncthreads();
    for (int st = 128; st > 0; st >>= 1) {
        if (threadIdx.x < st) r[threadIdx.x] += r[threadIdx.x + st];
        __syncthreads();
    }
    if (threadIdx.x == 0) out[b] = r[0] * (1.0f / (float)LEN) + bd[0];
}

// ---------------- launch -----------------------------------------------------
extern "C" void kernel_launch(void* const* d_in, const int* in_sizes, int n_in,
                              void* d_out, int out_size) {
    const float* u          = (const float*)d_in[0];
    const float* log_dt     = (const float*)d_in[1];
    const float* log_A_real = (const float*)d_in[2];
    const float* A_imag     = (const float*)d_in[3];
    const float* B_re       = (const float*)d_in[4];
    const float* B_im       = (const float*)d_in[5];
    const float* C_re       = (const float*)d_in[6];
    const float* C_im       = (const float*)d_in[7];
    const float* Dp         = (const float*)d_in[8];
    const float* W_out      = (const float*)d_in[9];
    const float* b_out      = (const float*)d_in[10];
    const float* W_dec      = (const float*)d_in[11];
    const float* b_dec      = (const float*)d_in[12];
    float* out = (float*)d_out;

    k_params<<<(DMODEL * DSTATE + 127) / 128, 128>>>(log_dt, log_A_real, A_imag,
                                                     B_re, B_im, C_re, C_im);
    k_packW<<<(8 * 32 * 2048) / 256, 256>>>(W_out);
    k_zero<<<(BATCH * DMODEL + 255) / 256, 256>>>();
    k_scan<<<(BATCH * DMODEL) / 4, 128>>>(u, Dp);
    dim3 gg(8, (BATCH * LEN) / 128);
    k_gemm<<<gg, 256>>>(b_out);
    k_final<<<BATCH, 256>>>(W_dec, b_dec, out);
}

// round 13
// speedup vs baseline: 1.0046x; 1.0046x over previous
#include <cuda_runtime.h>
#include <math.h>

#define BATCH   16
#define DMODEL  512
#define DSTATE  64
#define LEN     4096

// ---------------- scratch (device globals: no allocations allowed) ----------
__device__ __align__(16) float g_zr[DMODEL*DSTATE];
__device__ __align__(16) float g_zi[DMODEL*DSTATE];
__device__ __align__(16) float g_wr[DMODEL*DSTATE];
__device__ __align__(16) float g_wi[DMODEL*DSTATE];
__device__ __align__(16) float g_w2r[DMODEL*DSTATE];
__device__ __align__(16) float g_w2i[DMODEL*DSTATE];
__device__ __align__(16) float g_gelu[(size_t)BATCH*DMODEL*LEN];   // 128 MB
__device__ __align__(16) float g_pooled[BATCH*DMODEL];
// W pre-packed into mma fragment order (tf32 bits): [rblk8][kt32][h2][mf8][lane32][reg4]
__device__ __align__(16) unsigned int g_Wp[8*32*2048];

__device__ __forceinline__ unsigned int f2tf32(float x) {
    unsigned int r;
    asm("cvt.rna.tf32.f32 %0, %1;" : "=r"(r) : "f"(x));
    return r;
}

// ---------------- packed f32x2 helpers (sm_103a FFMA2 path) -----------------
typedef unsigned long long f32x2;
__device__ __forceinline__ f32x2 pk2(float lo, float hi) {
    f32x2 r; asm("mov.b64 %0, {%1, %2};" : "=l"(r) : "f"(lo), "f"(hi)); return r;
}
__device__ __forceinline__ void upk2(float& lo, float& hi, f32x2 v) {
    asm("mov.b64 {%0, %1}, %2;" : "=f"(lo), "=f"(hi) : "l"(v));
}
__device__ __forceinline__ f32x2 fma2(f32x2 a, f32x2 b, f32x2 c) {
    f32x2 d; asm("fma.rn.f32x2 %0, %1, %2, %3;" : "=l"(d) : "l"(a), "l"(b), "l"(c)); return d;
}
__device__ __forceinline__ f32x2 mul2(f32x2 a, f32x2 b) {
    f32x2 d; asm("mul.rn.f32x2 %0, %1, %2;" : "=l"(d) : "l"(a), "l"(b)); return d;
}
__device__ __forceinline__ f32x2 add2(f32x2 a, f32x2 b) {
    f32x2 d; asm("add.rn.f32x2 %0, %1, %2;" : "=l"(d) : "l"(a), "l"(b)); return d;
}

// ---------------- kernel 1: SSM constants (fp64 for phase accuracy) ---------
__global__ void k_params(const float* __restrict__ log_dt,
                         const float* __restrict__ log_A_real,
                         const float* __restrict__ A_imag,
                         const float* __restrict__ B_re,
                         const float* __restrict__ B_im,
                         const float* __restrict__ C_re,
                         const float* __restrict__ C_im) {
    int i = blockIdx.x * blockDim.x + threadIdx.x;
    if (i >= DMODEL * DSTATE) return;
    int d = i / DSTATE;
    double dt   = exp((double)log_dt[d]);
    double Ar   = -exp((double)log_A_real[i]);
    double Ai   = (double)A_imag[i];
    double dtAr = Ar * dt, dtAi = Ai * dt;
    double er = exp(dtAr);
    double zr = er * cos(dtAi), zi = er * sin(dtAi);
    double den  = Ar * Ar + Ai * Ai;
    double numr = zr - 1.0, numi = zi;
    double qr = (numr * Ar + numi * Ai) / den;
    double qi = (numi * Ar - numr * Ai) / den;
    double Br = (double)B_re[i], Bi = (double)B_im[i];
    double bbr = qr * Br - qi * Bi, bbi = qr * Bi + qi * Br;
    double Cr = (double)C_re[i], Ci = (double)C_im[i];
    double wr = Cr * bbr - Ci * bbi, wi = Cr * bbi + Ci * bbr;
    double eL = exp((double)LEN * dtAr);
    double ph = (double)LEN * dtAi;
    double zLr = eL * cos(ph), zLi = eL * sin(ph);
    double w2r = -(wr * zLr - wi * zLi);
    double w2i = -(wr * zLi + wi * zLr);
    g_zr[i] = (float)zr;  g_zi[i] = (float)zi;
    g_wr[i] = (float)wr;  g_wi[i] = (float)wi;
    g_w2r[i] = (float)w2r; g_w2i[i] = (float)w2i;
}

// ---------------- kernel 1b: pack W into tf32 mma fragment order ------------
__global__ void k_packW(const float* __restrict__ W) {
    int flat = blockIdx.x * blockDim.x + threadIdx.x;   // 524288 total
    int reg  = flat & 3;
    int lane = (flat >> 2) & 31;
    int mf8  = (flat >> 7) & 7;
    int h    = (flat >> 10) & 1;
    int kt   = (flat >> 11) & 31;
    int rb   = flat >> 16;
    int m = mf8 * 16 + (lane >> 2) + 8 * (reg & 1);
    int k = kt * 16 + h * 8 + (lane & 3) + 4 * (reg >> 1);
    int wrow = (m < 64) ? rb * 64 + m : 448 + rb * 64 + m;
    g_Wp[flat] = f2tf32(W[wrow * 512 + k]);
}

// ---------------- kernel 2: zero pooled accumulator -------------------------
__global__ void k_zero() {
    int i = blockIdx.x * blockDim.x + threadIdx.x;
    if (i < BATCH * DMODEL) g_pooled[i] = 0.0f;
}

// ---------------- kernel 3: packed Goertzel scan + skip + GELU --------------
// One warp per (b,d); 2 states per lane packed into f32x2 (n=lane, n=lane+32).
// Pass A: s(x) = u[x] + p s(x+1) + q s(x+2); H0 = s(0) - conj(z) s(1).
// Pass B: R(x) = p R(x+1) + q R(x+2) + c1 u[x+1] + c0 u[x+2],
//         c1 = w2r, c0 = -Re(conj(z) w2), primed from E(L-1) = w*H0.
#define ROWW 68   // floats per smem row (32 float2 + pad), 272B = 17*16B aligned

__global__ __launch_bounds__(128) void k_scan(const float* __restrict__ u,
                                              const float* __restrict__ Dp) {
    __shared__ __align__(16) float sbuf[4][32 * ROWW];

    int wid  = threadIdx.x >> 5;
    int lane = threadIdx.x & 31;
    int bd = blockIdx.x * 4 + wid;
    int d  = bd & (DMODEL - 1);
    const float* ub = u + (size_t)bd * LEN;
    float* gb = g_gelu + (size_t)bd * LEN;
    float* sbw = sbuf[wid];

    int dn0 = d * DSTATE + lane;
    int dn1 = dn0 + 32;
    float zra = g_zr[dn0], zia = g_zi[dn0];
    float zrb = g_zr[dn1], zib = g_zi[dn1];
    float pa = 2.0f * zra, qa = -fmaf(zra, zra, zia * zia);
    float pb = 2.0f * zrb, qb = -fmaf(zrb, zrb, zib * zib);
    float Dd = Dp[d];

    f32x2 pv = pk2(pa, pb), qv = pk2(qa, qb);

    // ---- pass A: packed Goertzel (2 FFMA2/step for both states) ----
    f32x2 s1v = 0ull, s2v = 0ull;
    for (int x0 = LEN - 32; x0 >= 0; x0 -= 32) {
        float ul = ub[x0 + lane];
        #pragma unroll
        for (int t = 31; t >= 0; --t) {
            float uu = __shfl_sync(0xffffffffu, ul, t);
            f32x2 uv = pk2(uu, uu);
            f32x2 nv = fma2(pv, s1v, fma2(qv, s2v, uv));
            s2v = s1v; s1v = nv;
        }
    }
    float s1a, s1b, s2a, s2b;
    upk2(s1a, s1b, s1v);
    upk2(s2a, s2b, s2v);

    // ---- boundary priming (complex, once, scalar) ----
    float uL1 = __ldg(ub + LEN - 1);
    float c1a, c0a, r1a, r2a, c1b, c0b, r1b, r2b;
    {
        float wr = g_wr[dn0], wi = g_wi[dn0];
        float w2r = g_w2r[dn0], w2i = g_w2i[dn0];
        float H0r = fmaf(-zra, s2a, s1a), H0i = zia * s2a;
        float mr = fmaf(wr, H0r, -wi * H0i);
        float mi = fmaf(wr, H0i,  wi * H0r);
        float RL1 = mr;
        float RL2 = fmaf(zra, mr, fmaf(-zia, mi, w2r * uL1));
        c1a = w2r;
        c0a = -fmaf(zra, w2r, zia * w2i);
        float invq = 1.0f / qa;
        r1a = (RL2 - pa * RL1 - c1a * uL1) * invq;   // ghost R(L)
        r2a = (RL1 - pa * r1a) * invq;               // ghost R(L+1)
    }
    {
        float wr = g_wr[dn1], wi = g_wi[dn1];
        float w2r = g_w2r[dn1], w2i = g_w2i[dn1];
        float H0r = fmaf(-zrb, s2b, s1b), H0i = zib * s2b;
        float mr = fmaf(wr, H0r, -wi * H0i);
        float mi = fmaf(wr, H0i,  wi * H0r);
        float RL1 = mr;
        float RL2 = fmaf(zrb, mr, fmaf(-zib, mi, w2r * uL1));
        c1b = w2r;
        c0b = -fmaf(zrb, w2r, zib * w2i);
        float invq = 1.0f / qb;
        r1b = (RL2 - pb * RL1 - c1b * uL1) * invq;
        r2b = (RL1 - pb * r1b) * invq;
    }

    f32x2 c1v = pk2(c1a, c1b), c0v = pk2(c0a, c0b);
    f32x2 r1v = pk2(r1a, r1b), r2v = pk2(r2a, r2b);
    f32x2 u1v = 0ull, u2v = 0ull;                    // ghost u[L], u[L+1]

    // ---- pass B: packed real 2nd-order emission (4 FFMA2/step) ----
    for (int x0 = LEN - 32; x0 >= 0; x0 -= 32) {
        float ul = ub[x0 + lane];
        #pragma unroll
        for (int t = 31; t >= 0; --t) {
            float uu = __shfl_sync(0xffffffffu, ul, t);
            f32x2 uv = pk2(uu, uu);
            f32x2 tv = fma2(c1v, u1v, mul2(c0v, u2v));
            tv = fma2(qv, r2v, tv);
            f32x2 Rv = fma2(pv, r1v, tv);
            *reinterpret_cast<f32x2*>(sbw + t * ROWW + lane * 2) = Rv;  // STS.64 packed
            r2v = r1v; r1v = Rv;
            u2v = u1v; u1v = uv;
        }
        __syncwarp();
        // reduce 64 states = 32 packed pairs in row `lane` (conflict-free LDS.128)
        const ulonglong2* row = reinterpret_cast<const ulonglong2*>(sbw + lane * ROWW);
        f32x2 acc0 = 0ull, acc1 = 0ull;
        #pragma unroll
        for (int k = 0; k < 16; ++k) {
            ulonglong2 v = row[k];
            acc0 = add2(acc0, v.x);
            acc1 = add2(acc1, v.y);
        }
        f32x2 accv = add2(acc0, acc1);
        float alo, ahi;
        upk2(alo, ahi, accv);
        float yv = fmaf(Dd, ul, alo + ahi);
        float gv = 0.5f * yv * (1.0f + erff(yv * 0.7071067811865475f));
        gb[x0 + lane] = gv;
        __syncwarp();
    }
}

// ---------------- kernel 4: tf32 tensor-core GEMM + GLU + mean fused --------
#define SA_STRIDE 2048
#define SB_GRP    66
#define SB_STRIDE (32*SB_GRP)

__device__ __forceinline__ void mma_tf32(float* c, const uint4 a, const uint2 b) {
    asm volatile(
        "mma.sync.aligned.m16n8k8.row.col.f32.tf32.tf32.f32 "
        "{%0,%1,%2,%3}, {%4,%5,%6,%7}, {%8,%9}, {%0,%1,%2,%3};"
        : "+f"(c[0]), "+f"(c[1]), "+f"(c[2]), "+f"(c[3])
        : "r"(a.x), "r"(a.y), "r"(a.z), "r"(a.w), "r"(b.x), "r"(b.y));
}

__global__ __launch_bounds__(256) void k_gemm(const float* __restrict__ bout) {
    __shared__ __align__(16) float sh[8576];
    float* sA = sh;
    float* sB = sh + 2 * SA_STRIDE;

    int tid = threadIdx.x;
    int w = tid >> 5, lane = tid & 31;
    int wm = w & 1, wn = w >> 1;
    int rblk = blockIdx.x;
    int nblk = blockIdx.y;
    int col0 = nblk * 128;
    int b = col0 >> 12;
    const float* yg = g_gelu + (size_t)b * DMODEL * LEN + (col0 & (LEN - 1));
    const unsigned int* Wp = g_Wp + rblk * (32 * 2048);

    float acc[4][4][4];
    #pragma unroll
    for (int i = 0; i < 4; ++i)
        #pragma unroll
        for (int j = 0; j < 4; ++j)
            #pragma unroll
            for (int r = 0; r < 4; ++r) acc[i][j][r] = 0.0f;

    #pragma unroll
    for (int i = 0; i < 2; ++i) {
        int ia = tid + i * 256;
        uint4 va = *reinterpret_cast<const uint4*>(Wp + (size_t)ia * 4);
        *reinterpret_cast<uint4*>(reinterpret_cast<unsigned int*>(sA) + ia * 4) = va;
        int k = ia >> 5, n0 = (ia & 31) << 2;
        float4 vb = *reinterpret_cast<const float4*>(yg + (size_t)k * LEN + n0);
        float v[4] = {vb.x, vb.y, vb.z, vb.w};
        int h = k >> 3, kk = k & 3, reg = (k >> 2) & 1;
        #pragma unroll
        for (int e = 0; e < 4; ++e) {
            int nn = n0 + e;
            int l = ((nn & 7) << 2) | kk;
            sB[(h * 16 + (nn >> 3)) * SB_GRP + l * 2 + reg] = __uint_as_float(f2tf32(v[e]));
        }
    }
    __syncthreads();

    for (int kt = 0; kt < 32; ++kt) {
        int buf = kt & 1;
        bool has = kt < 31;
        uint4 pa[2]; float4 pb[2];
        if (has) {
            #pragma unroll
            for (int i = 0; i < 2; ++i) {
                int ia = tid + i * 256;
                pa[i] = *reinterpret_cast<const uint4*>(Wp + (size_t)(kt + 1) * 2048 + (size_t)ia * 4);
                int k = ia >> 5, n0 = (ia & 31) << 2;
                pb[i] = *reinterpret_cast<const float4*>(yg + (size_t)((kt + 1) * 16 + k) * LEN + n0);
            }
        }
        const float* sAb = sA + buf * SA_STRIDE;
        const float* sBb = sB + buf * SB_STRIDE;
        #pragma unroll
        for (int h = 0; h < 2; ++h) {
            uint4 af[4]; uint2 bf[4];
            #pragma unroll
            for (int mf = 0; mf < 4; ++mf)
                af[mf] = *reinterpret_cast<const uint4*>(sAb + ((h * 8 + wm * 4 + mf) * 128 + lane * 4));
            #pragma unroll
            for (int nf = 0; nf < 4; ++nf)
                bf[nf] = *reinterpret_cast<const uint2*>(sBb + (h * 16 + wn * 4 + nf) * SB_GRP + lane * 2);
            #pragma unroll
            for (int mf = 0; mf < 4; ++mf)
                #pragma unroll
                for (int nf = 0; nf < 4; ++nf)
                    mma_tf32(acc[mf][nf], af[mf], bf[nf]);
        }
        if (has) {
            int nb = buf ^ 1;
            #pragma unroll
            for (int i = 0; i < 2; ++i) {
                int ia = tid + i * 256;
                *reinterpret_cast<uint4*>(reinterpret_cast<unsigned int*>(sA + nb * SA_STRIDE) + ia * 4) = pa[i];
                int k = ia >> 5, n0 = (ia & 31) << 2;
                float v[4] = {pb[i].x, pb[i].y, pb[i].z, pb[i].w};
                int h = k >> 3, kk = k & 3, reg = (k >> 2) & 1;
                float* sBn = sB + nb * SB_STRIDE;
                #pragma unroll
                for (int e = 0; e < 4; ++e) {
                    int nn = n0 + e;
                    int l = ((nn & 7) << 2) | kk;
                    sBn[(h * 16 + (nn >> 3)) * SB_GRP + l * 2 + reg] = __uint_as_float(f2tf32(v[e]));
                }
            }
        }
        __syncthreads();
    }

    float* Sg  = sh;
    float* red = sh + 64 * 129;

    if (wm == 1) {
        #pragma unroll
        for (int mf = 0; mf < 4; ++mf)
            #pragma unroll
            for (int hi = 0; hi < 2; ++hi) {
                int row = mf * 16 + (lane >> 2) + 8 * hi;
                float bo = bout[512 + rblk * 64 + row];
                #pragma unroll
                for (int nf = 0; nf < 4; ++nf)
                    #pragma unroll
                    for (int c01 = 0; c01 < 2; ++c01) {
                        int col = wn * 32 + nf * 8 + ((lane & 3) << 1) + c01;
                        float gv = acc[mf][nf][2 * hi + c01] + bo;
                        Sg[row * 129 + col] = 1.0f / (1.0f + expf(-gv));
                    }
            }
    }
    __syncthreads();
    if (wm == 0) {
        #pragma unroll
        for (int mf = 0; mf < 4; ++mf)
            #pragma unroll
            for (int hi = 0; hi < 2; ++hi) {
                int row = mf * 16 + (lane >> 2) + 8 * hi;
                float bo = bout[rblk * 64 + row];
                float rs = 0.0f;
                #pragma unroll
                for (int nf = 0; nf < 4; ++nf)
                    #pragma unroll
                    for (int c01 = 0; c01 < 2; ++c01) {
                        int col = wn * 32 + nf * 8 + ((lane & 3) << 1) + c01;
                        rs += (acc[mf][nf][2 * hi + c01] + bo) * Sg[row * 129 + col];
                    }
                rs += __shfl_xor_sync(0xffffffffu, rs, 1);
                rs += __shfl_xor_sync(0xffffffffu, rs, 2);
                if ((lane & 3) == 0) red[row * 4 + wn] = rs;
            }
    }
    __syncthreads();
    if (tid < 64) {
        float s = red[tid * 4] + red[tid * 4 + 1] + red[tid * 4 + 2] + red[tid * 4 + 3];
        atomicAdd(&g_pooled[b * DMODEL + rblk * 64 + tid], s);
    }
}

// ---------------- kernel 5: mean scale + decoder ----------------------------
__global__ void k_final(const float* __restrict__ Wd,
                        const float* __restrict__ bd,
                        float* __restrict__ out) {
    int b = blockIdx.x;
    __shared__ float r[256];
    float s = 0.0f;
    for (int c = threadIdx.x; c < DMODEL; c += 256)
        s += Wd[c] * g_pooled[b * DMODEL + c];
    r[threadIdx.x] = s;
    __syncthreads();
    for (int st = 128; st > 0; st >>= 1) {
        if (threadIdx.x < st) r[threadIdx.x] += r[threadIdx.x + st];
        __syncthreads();
    }
    if (threadIdx.x == 0) out[b] = r[0] * (1.0f / (float)LEN) + bd[0];
}

// ---------------- launch -----------------------------------------------------
extern "C" void kernel_launch(void* const* d_in, const int* in_sizes, int n_in,
                              void* d_out, int out_size) {
    const float* u          = (const float*)d_in[0];
    const float* log_dt     = (const float*)d_in[1];
    const float* log_A_real = (const float*)d_in[2];
    const float* A_imag     = (const float*)d_in[3];
    const float* B_re       = (const float*)d_in[4];
    const float* B_im       = (const float*)d_in[5];
    const float* C_re       = (const float*)d_in[6];
    const float* C_im       = (const float*)d_in[7];
    const float* Dp         = (const float*)d_in[8];
    const float* W_out      = (const float*)d_in[9];
    const float* b_out      = (const float*)d_in[10];
    const float* W_dec      = (const float*)d_in[11];
    const float* b_dec      = (const float*)d_in[12];
    float* out = (float*)d_out;

    k_params<<<(DMODEL * DSTATE + 127) / 128, 128>>>(log_dt, log_A_real, A_imag,
                                                     B_re, B_im, C_re, C_im);
    k_packW<<<(8 * 32 * 2048) / 256, 256>>>(W_out);
    k_zero<<<(BATCH * DMODEL + 255) / 256, 256>>>();
    k_scan<<<(BATCH * DMODEL) / 4, 128>>>(u, Dp);
    dim3 gg(8, (BATCH * LEN) / 128);
    k_gemm<<<gg, 256>>>(b_out);
    k_final<<<BATCH, 256>>>(W_dec, b_dec, out);
}

// round 14
// speedup vs baseline: 1.5221x; 1.5151x over previous
#include <cuda_runtime.h>
#include <math.h>

#define BATCH   16
#define DMODEL  512
#define DSTATE  64
#define LEN     4096

// ---------------- scratch (device globals: no allocations allowed) ----------
__device__ __align__(16) float g_zr[DMODEL*DSTATE];
__device__ __align__(16) float g_zi[DMODEL*DSTATE];
__device__ __align__(16) float g_wr[DMODEL*DSTATE];
__device__ __align__(16) float g_wi[DMODEL*DSTATE];
__device__ __align__(16) float g_zTr[DMODEL*DSTATE];   // z^64
__device__ __align__(16) float g_zTi[DMODEL*DSTATE];
__device__ __align__(16) float g_Kp[DMODEL*64];        // K'[lag] per d
__device__ __align__(16) float g_gelu[(size_t)BATCH*DMODEL*LEN];   // 128 MB
__device__ __align__(16) float g_pooled[BATCH*DMODEL];
// W_out pre-packed (tf32): [rblk8][kt32][h2][mf8][lane32][reg4]
__device__ __align__(16) unsigned int g_Wp[8*32*2048];
// scan stage-1 A: per d [mf8][kf8][lane32][reg4]; rows 0..63 Re z^s, 64..127 Im z^s
__device__ __align__(16) unsigned int g_VSp[(size_t)DMODEL*8192];
// scan stage-3 A: per d [mf4][kf24][lane32][reg4];
// cols 0..63 K'[t-s] Toeplitz, 64..127 Re z^{63-t}, 128..191 -Im z^{63-t}
__device__ __align__(16) unsigned int g_W2p[(size_t)DMODEL*12288];

__device__ __forceinline__ unsigned int f2tf32(float x) {
    unsigned int r;
    asm("cvt.rna.tf32.f32 %0, %1;" : "=r"(r) : "f"(x));
    return r;
}

// fragment slot helpers (match k_packW / k_gemm conventions, validated)
__device__ __forceinline__ int aidx(int row, int col, int kfN) {
    int mf = row >> 4, kf = col >> 3;
    int lane = (row & 7) * 4 + (col & 3);
    int reg  = ((row >> 3) & 1) + 2 * ((col >> 2) & 1);
    return (mf * kfN + kf) * 128 + lane * 4 + reg;
}
__device__ __forceinline__ int bidx(int k, int c) {   // B2: 24 kf x 8 nf
    int lane = (c & 7) * 4 + (k & 3);
    int reg  = (k >> 2) & 1;
    return (((k >> 3) * 8 + (c >> 3)) * 32 + lane) * 2 + reg;
}

// ---------------- kernel 1: SSM constants (fp64 for phase accuracy) ---------
__global__ void k_params(const float* __restrict__ log_dt,
                         const float* __restrict__ log_A_real,
                         const float* __restrict__ A_imag,
                         const float* __restrict__ B_re,
                         const float* __restrict__ B_im,
                         const float* __restrict__ C_re,
                         const float* __restrict__ C_im) {
    int i = blockIdx.x * blockDim.x + threadIdx.x;
    if (i >= DMODEL * DSTATE) return;
    int d = i / DSTATE;
    double dt   = exp((double)log_dt[d]);
    double Ar   = -exp((double)log_A_real[i]);
    double Ai   = (double)A_imag[i];
    double dtAr = Ar * dt, dtAi = Ai * dt;
    double er = exp(dtAr);
    double zr = er * cos(dtAi), zi = er * sin(dtAi);
    double den  = Ar * Ar + Ai * Ai;
    double numr = zr - 1.0, numi = zi;
    double qr = (numr * Ar + numi * Ai) / den;
    double qi = (numi * Ar - numr * Ai) / den;
    double Br = (double)B_re[i], Bi = (double)B_im[i];
    double bbr = qr * Br - qi * Bi, bbi = qr * Bi + qi * Br;
    double Cr = (double)C_re[i], Ci = (double)C_im[i];
    double wr = Cr * bbr - Ci * bbi, wi = Cr * bbi + Ci * bbr;
    double eT = exp(64.0 * dtAr);
    double phT = 64.0 * dtAi;
    g_zr[i] = (float)zr;   g_zi[i] = (float)zi;
    g_wr[i] = (float)wr;   g_wi[i] = (float)wi;
    g_zTr[i] = (float)(eT * cos(phT));
    g_zTi[i] = (float)(eT * sin(phT));
}

// ---------------- kernel 1b: pack W_out into tf32 mma fragment order --------
__global__ void k_packW(const float* __restrict__ W) {
    int flat = blockIdx.x * blockDim.x + threadIdx.x;   // 524288 total
    int reg  = flat & 3;
    int lane = (flat >> 2) & 31;
    int mf8  = (flat >> 7) & 7;
    int h    = (flat >> 10) & 1;
    int kt   = (flat >> 11) & 31;
    int rb   = flat >> 16;
    int m = mf8 * 16 + (lane >> 2) + 8 * (reg & 1);
    int k = kt * 16 + h * 8 + (lane & 3) + 4 * (reg >> 1);
    int wrow = (m < 64) ? rb * 64 + m : 448 + rb * 64 + m;
    g_Wp[flat] = f2tf32(W[wrow * 512 + k]);
}

// ---------------- scan-matrix builders --------------------------------------
// VS: row n -> Re z^s, row 64+n -> Im z^s (s = 0..63)
__global__ void k_matVS() {
    int id = blockIdx.x * blockDim.x + threadIdx.x;
    if (id >= DMODEL * DSTATE) return;
    int d = id >> 6, n = id & 63, dn = d * 64 + n;
    float zr = g_zr[dn], zi = g_zi[dn];
    unsigned int* base = g_VSp + (size_t)d * 8192;
    float vr = 1.0f, vi = 0.0f;
    for (int s = 0; s < 64; ++s) {
        base[aidx(n,      s, 8)] = f2tf32(vr);
        base[aidx(64 + n, s, 8)] = f2tf32(vi);
        float nr = vr * zr - vi * zi;
        vi = vr * zi + vi * zr; vr = nr;
    }
}

// K'[lag] = Re sum_n w_n z_n^{L-1-lag} = Re sum_n (w zT^63) z^{63-lag}
__global__ void k_matK() {   // <<<512, 64>>>
    __shared__ float sK[64 * 65];       // [lag][state]
    int d = blockIdx.x, n = threadIdx.x, dn = d * 64 + n;
    float zr = g_zr[dn], zi = g_zi[dn];
    float tr = g_zTr[dn], ti = g_zTi[dn];
    float cr = 1.0f, ci = 0.0f;
    int e = 63;                          // zT^63 by squaring
    while (e) {
        if (e & 1) { float nr = cr * tr - ci * ti; ci = cr * ti + ci * tr; cr = nr; }
        float nr2 = tr * tr - ti * ti; ti = 2.0f * tr * ti; tr = nr2;
        e >>= 1;
    }
    float wr = g_wr[dn], wi = g_wi[dn];
    float br = wr * cr - wi * ci, bi = wr * ci + wi * cr;   // w * z^{L-64}... * z^m below
    for (int m = 0; m < 64; ++m) {       // value = w zT^63 z^m -> lag = 63-m
        sK[(63 - m) * 65 + n] = br;
        float nr = br * zr - bi * zi; bi = br * zi + bi * zr; br = nr;
    }
    __syncthreads();
    float s = 0.0f;
    for (int k2 = 0; k2 < 64; ++k2) s += sK[n * 65 + k2];
    g_Kp[d * 64 + n] = s;                // K'[lag = n]
}

// W2 cols 0..63: Kmat[t][s] = K'[t-s] (t>=s) else 0
__global__ void k_matW2K() {
    int id = blockIdx.x * blockDim.x + threadIdx.x;   // 512*4096
    if (id >= DMODEL * 4096) return;
    int d = id >> 12, t = (id >> 6) & 63, s = id & 63;
    float v = (t >= s) ? g_Kp[d * 64 + (t - s)] : 0.0f;
    g_W2p[(size_t)d * 12288 + aidx(t, s, 24)] = f2tf32(v);
}

// W2 cols 64+n: Re z^{63-t}; cols 128+n: -Im z^{63-t}
__global__ void k_matW2V() {
    int id = blockIdx.x * blockDim.x + threadIdx.x;
    if (id >= DMODEL * DSTATE) return;
    int d = id >> 6, n = id & 63, dn = d * 64 + n;
    float zr = g_zr[dn], zi = g_zi[dn];
    unsigned int* base = g_W2p + (size_t)d * 12288;
    float vr = 1.0f, vi = 0.0f;          // z^m, t = 63-m
    for (int m = 0; m < 64; ++m) {
        int t = 63 - m;
        base[aidx(t,  64 + n, 24)] = f2tf32(vr);
        base[aidx(t, 128 + n, 24)] = f2tf32(-vi);
        float nr = vr * zr - vi * zi;
        vi = vr * zi + vi * zr; vr = nr;
    }
}

// ---------------- kernel 2: zero pooled accumulator -------------------------
__global__ void k_zero() {
    int i = blockIdx.x * blockDim.x + threadIdx.x;
    if (i < BATCH * DMODEL) g_pooled[i] = 0.0f;
}

// ---------------- mma wrapper -----------------------------------------------
__device__ __forceinline__ void mma_tf32(float* c, const uint4 a, const uint2 b) {
    asm volatile(
        "mma.sync.aligned.m16n8k8.row.col.f32.tf32.tf32.f32 "
        "{%0,%1,%2,%3}, {%4,%5,%6,%7}, {%8,%9}, {%0,%1,%2,%3};"
        : "+f"(c[0]), "+f"(c[1]), "+f"(c[2]), "+f"(c[3])
        : "r"(a.x), "r"(a.y), "r"(a.z), "r"(a.w), "r"(b.x), "r"(b.y));
}

// ---------------- kernel 3: tensor-core chunked scan + skip + GELU ----------
// Block (128 thr) per (b,d). Dyn smem: B2 frags 12288 uints | sS 128x66 floats.
#define SCAN_SMEM ((12288 + 128*66) * 4)

__global__ __launch_bounds__(128) void k_scan_tc(const float* __restrict__ u,
                                                 const float* __restrict__ Dp) {
    extern __shared__ unsigned int smemu[];
    unsigned int* sB2 = smemu;                 // [U kf0..7 | GR kf8..15 | GI kf16..23]
    float* sS = (float*)(smemu + 12288);       // S then P (128 x 66)
    float* sY = sS;                            // y bounce (64 x 65), reused

    int tid = threadIdx.x, w = tid >> 5, lane = tid & 31;
    int bd = blockIdx.x, d = bd & (DMODEL - 1);
    const float* ub = u + (size_t)bd * LEN;
    float* gb = g_gelu + (size_t)bd * LEN;
    float Dd = Dp[d];

    // ---- stage 0: pack U into B fragments (k=s, n=c) ----
    #pragma unroll
    for (int i = 0; i < 32; ++i) {
        int x = tid + (i << 7);
        int s = x & 63, c = x >> 6;
        sB2[bidx(s, c)] = f2tf32(ub[x]);
    }
    __syncthreads();

    // ---- stage 1: S(128x64) = VS @ U ----
    {
        float acc[16][4];
        #pragma unroll
        for (int a = 0; a < 16; ++a)
            #pragma unroll
            for (int r = 0; r < 4; ++r) acc[a][r] = 0.0f;
        const uint4* Ab = (const uint4*)(g_VSp + (size_t)d * 8192);
        const uint2* Bb = (const uint2*)sB2;
        #pragma unroll
        for (int kf = 0; kf < 8; ++kf) {
            uint4 a0 = Ab[((2 * w)     * 8 + kf) * 32 + lane];
            uint4 a1 = Ab[((2 * w + 1) * 8 + kf) * 32 + lane];
            #pragma unroll
            for (int nf = 0; nf < 8; ++nf) {
                uint2 bf = Bb[(kf * 8 + nf) * 32 + lane];
                mma_tf32(acc[nf],     a0, bf);
                mma_tf32(acc[8 + nf], a1, bf);
            }
        }
        #pragma unroll
        for (int mi = 0; mi < 2; ++mi)
            #pragma unroll
            for (int nf = 0; nf < 8; ++nf)
                #pragma unroll
                for (int r = 0; r < 4; ++r) {
                    int row = 32 * w + 16 * mi + (lane >> 2) + 8 * (r >> 1);
                    int col = nf * 8 + 2 * (lane & 3) + (r & 1);
                    sS[row * 66 + col] = acc[mi * 8 + nf][r];
                }
    }
    __syncthreads();

    // ---- stage 2: prefix P_c and Gamma_c (threads 0..63, state n) ----
    if (tid < 64) {
        int n = tid, dn = d * 64 + n;
        float zTr = g_zTr[dn], zTi = g_zTi[dn];
        float wr = g_wr[dn],  wi = g_wi[dn];
        float* rR = sS + n * 66;
        float* rI = sS + (64 + n) * 66;
        float Pr = 0.f, Pi = 0.f, dr = 1.f, di = 0.f;      // dc = zT^c
        for (int c = 0; c < 64; ++c) {
            float sr = rR[c], si = rI[c];
            rR[c] = Pr; rI[c] = Pi;                        // store P_c (sum c'<c)
            Pr += dr * sr - di * si;
            Pi += dr * si + di * sr;
            float ndr = dr * zTr - di * zTi;
            di = dr * zTi + di * zTr; dr = ndr;
        }
        float er = wr, ei = wi;                            // w * zT^{63-c}, c=63
        for (int c = 63; c >= 0; --c) {
            float pr = rR[c], pi = rI[c];
            float Gr = er * pr - ei * pi;
            float Gi = er * pi + ei * pr;
            sB2[bidx(64 + n, c)]  = f2tf32(Gr);
            sB2[bidx(128 + n, c)] = f2tf32(Gi);
            float ner = er * zTr - ei * zTi;
            ei = er * zTi + ei * zTr; er = ner;
        }
    }
    __syncthreads();

    // ---- stage 3: y(64x64) = W2(64x192) @ [U; GR; GI] ----
    float acc2[8][4];
    #pragma unroll
    for (int a = 0; a < 8; ++a)
        #pragma unroll
        for (int r = 0; r < 4; ++r) acc2[a][r] = 0.0f;
    {
        const uint4* A2 = (const uint4*)(g_W2p + (size_t)d * 12288);
        const uint2* Bb = (const uint2*)sB2;
        #pragma unroll
        for (int kf = 0; kf < 24; ++kf) {
            uint4 a = A2[(w * 24 + kf) * 32 + lane];
            #pragma unroll
            for (int nf = 0; nf < 8; ++nf) {
                uint2 bf = Bb[(kf * 8 + nf) * 32 + lane];
                mma_tf32(acc2[nf], a, bf);
            }
        }
    }
    // bounce y through smem for coalesced epilogue
    #pragma unroll
    for (int nf = 0; nf < 8; ++nf)
        #pragma unroll
        for (int r = 0; r < 4; ++r) {
            int t = 16 * w + (lane >> 2) + 8 * (r >> 1);
            int c = nf * 8 + 2 * (lane & 3) + (r & 1);
            sY[t * 65 + c] = acc2[nf][r];
        }
    __syncthreads();
    #pragma unroll
    for (int i = 0; i < 32; ++i) {
        int x = tid + (i << 7);
        int t = x & 63, c = x >> 6;
        float yv = fmaf(Dd, ub[x], sY[t * 65 + c]);
        float gv = 0.5f * yv * (1.0f + erff(yv * 0.7071067811865475f));
        gb[x] = gv;
    }
}

// ---------------- kernel 4: tf32 tensor-core GEMM + GLU + mean fused --------
#define SA_STRIDE 2048
#define SB_GRP    66
#define SB_STRIDE (32*SB_GRP)

__global__ __launch_bounds__(256) void k_gemm(const float* __restrict__ bout) {
    __shared__ __align__(16) float sh[8576];
    float* sA = sh;
    float* sB = sh + 2 * SA_STRIDE;

    int tid = threadIdx.x;
    int w = tid >> 5, lane = tid & 31;
    int wm = w & 1, wn = w >> 1;
    int rblk = blockIdx.x;
    int nblk = blockIdx.y;
    int col0 = nblk * 128;
    int b = col0 >> 12;
    const float* yg = g_gelu + (size_t)b * DMODEL * LEN + (col0 & (LEN - 1));
    const unsigned int* Wp = g_Wp + rblk * (32 * 2048);

    float acc[4][4][4];
    #pragma unroll
    for (int i = 0; i < 4; ++i)
        #pragma unroll
        for (int j = 0; j < 4; ++j)
            #pragma unroll
            for (int r = 0; r < 4; ++r) acc[i][j][r] = 0.0f;

    #pragma unroll
    for (int i = 0; i < 2; ++i) {
        int ia = tid + i * 256;
        uint4 va = *reinterpret_cast<const uint4*>(Wp + (size_t)ia * 4);
        *reinterpret_cast<uint4*>(reinterpret_cast<unsigned int*>(sA) + ia * 4) = va;
        int k = ia >> 5, n0 = (ia & 31) << 2;
        float4 vb = *reinterpret_cast<const float4*>(yg + (size_t)k * LEN + n0);
        float v[4] = {vb.x, vb.y, vb.z, vb.w};
        int h = k >> 3, kk = k & 3, reg = (k >> 2) & 1;
        #pragma unroll
        for (int e = 0; e < 4; ++e) {
            int nn = n0 + e;
            int l = ((nn & 7) << 2) | kk;
            sB[(h * 16 + (nn >> 3)) * SB_GRP + l * 2 + reg] = __uint_as_float(f2tf32(v[e]));
        }
    }
    __syncthreads();

    for (int kt = 0; kt < 32; ++kt) {
        int buf = kt & 1;
        bool has = kt < 31;
        uint4 pa[2]; float4 pb[2];
        if (has) {
            #pragma unroll
            for (int i = 0; i < 2; ++i) {
                int ia = tid + i * 256;
                pa[i] = *reinterpret_cast<const uint4*>(Wp + (size_t)(kt + 1) * 2048 + (size_t)ia * 4);
                int k = ia >> 5, n0 = (ia & 31) << 2;
                pb[i] = *reinterpret_cast<const float4*>(yg + (size_t)((kt + 1) * 16 + k) * LEN + n0);
            }
        }
        const float* sAb = sA + buf * SA_STRIDE;
        const float* sBb = sB + buf * SB_STRIDE;
        #pragma unroll
        for (int h = 0; h < 2; ++h) {
            uint4 af[4]; uint2 bf[4];
            #pragma unroll
            for (int mf = 0; mf < 4; ++mf)
                af[mf] = *reinterpret_cast<const uint4*>(sAb + ((h * 8 + wm * 4 + mf) * 128 + lane * 4));
            #pragma unroll
            for (int nf = 0; nf < 4; ++nf)
                bf[nf] = *reinterpret_cast<const uint2*>(sBb + (h * 16 + wn * 4 + nf) * SB_GRP + lane * 2);
            #pragma unroll
            for (int mf = 0; mf < 4; ++mf)
                #pragma unroll
                for (int nf = 0; nf < 4; ++nf)
                    mma_tf32(acc[mf][nf], af[mf], bf[nf]);
        }
        if (has) {
            int nb = buf ^ 1;
            #pragma unroll
            for (int i = 0; i < 2; ++i) {
                int ia = tid + i * 256;
                *reinterpret_cast<uint4*>(reinterpret_cast<unsigned int*>(sA + nb * SA_STRIDE) + ia * 4) = pa[i];
                int k = ia >> 5, n0 = (ia & 31) << 2;
                float v[4] = {pb[i].x, pb[i].y, pb[i].z, pb[i].w};
                int h = k >> 3, kk = k & 3, reg = (k >> 2) & 1;
                float* sBn = sB + nb * SB_STRIDE;
                #pragma unroll
                for (int e = 0; e < 4; ++e) {
                    int nn = n0 + e;
                    int l = ((nn & 7) << 2) | kk;
                    sBn[(h * 16 + (nn >> 3)) * SB_GRP + l * 2 + reg] = __uint_as_float(f2tf32(v[e]));
                }
            }
        }
        __syncthreads();
    }

    float* Sg  = sh;
    float* red = sh + 64 * 129;

    if (wm == 1) {
        #pragma unroll
        for (int mf = 0; mf < 4; ++mf)
            #pragma unroll
            for (int hi = 0; hi < 2; ++hi) {
                int row = mf * 16 + (lane >> 2) + 8 * hi;
                float bo = bout[512 + rblk * 64 + row];
                #pragma unroll
                for (int nf = 0; nf < 4; ++nf)
                    #pragma unroll
                    for (int c01 = 0; c01 < 2; ++c01) {
                        int col = wn * 32 + nf * 8 + ((lane & 3) << 1) + c01;
                        float gv = acc[mf][nf][2 * hi + c01] + bo;
                        Sg[row * 129 + col] = 1.0f / (1.0f + expf(-gv));
                    }
            }
    }
    __syncthreads();
    if (wm == 0) {
        #pragma unroll
        for (int mf = 0; mf < 4; ++mf)
            #pragma unroll
            for (int hi = 0; hi < 2; ++hi) {
                int row = mf * 16 + (lane >> 2) + 8 * hi;
                float bo = bout[rblk * 64 + row];
                float rs = 0.0f;
                #pragma unroll
                for (int nf = 0; nf < 4; ++nf)
                    #pragma unroll
                    for (int c01 = 0; c01 < 2; ++c01) {
                        int col = wn * 32 + nf * 8 + ((lane & 3) << 1) + c01;
                        rs += (acc[mf][nf][2 * hi + c01] + bo) * Sg[row * 129 + col];
                    }
                rs += __shfl_xor_sync(0xffffffffu, rs, 1);
                rs += __shfl_xor_sync(0xffffffffu, rs, 2);
                if ((lane & 3) == 0) red[row * 4 + wn] = rs;
            }
    }
    __syncthreads();
    if (tid < 64) {
        float s = red[tid * 4] + red[tid * 4 + 1] + red[tid * 4 + 2] + red[tid * 4 + 3];
        atomicAdd(&g_pooled[b * DMODEL + rblk * 64 + tid], s);
    }
}

// ---------------- kernel 5: mean scale + decoder ----------------------------
__global__ void k_final(const float* __restrict__ Wd,
                        const float* __restrict__ bd,
                        float* __restrict__ out) {
    int b = blockIdx.x;
    __shared__ float r[256];
    float s = 0.0f;
    for (int c = threadIdx.x; c < DMODEL; c += 256)
        s += Wd[c] * g_pooled[b * DMODEL + c];
    r[threadIdx.x] = s;
    __syncthreads();
    for (int st = 128; st > 0; st >>= 1) {
        if (threadIdx.x < st) r[threadIdx.x] += r[threadIdx.x + st];
        __syncthreads();
    }
    if (threadIdx.x == 0) out[b] = r[0] * (1.0f / (float)LEN) + bd[0];
}

// ---------------- launch -----------------------------------------------------
extern "C" void kernel_launch(void* const* d_in, const int* in_sizes, int n_in,
                              void* d_out, int out_size) {
    const float* u          = (const float*)d_in[0];
    const float* log_dt     = (const float*)d_in[1];
    const float* log_A_real = (const float*)d_in[2];
    const float* A_imag     = (const float*)d_in[3];
    const float* B_re       = (const float*)d_in[4];
    const float* B_im       = (const float*)d_in[5];
    const float* C_re       = (const float*)d_in[6];
    const float* C_im       = (const float*)d_in[7];
    const float* Dp         = (const float*)d_in[8];
    const float* W_out      = (const float*)d_in[9];
    const float* b_out      = (const float*)d_in[10];
    const float* W_dec      = (const float*)d_in[11];
    const float* b_dec      = (const float*)d_in[12];
    float* out = (float*)d_out;

    cudaFuncSetAttribute(k_scan_tc, cudaFuncAttributeMaxDynamicSharedMemorySize,
                         SCAN_SMEM);

    k_params<<<(DMODEL * DSTATE + 127) / 128, 128>>>(log_dt, log_A_real, A_imag,
                                                     B_re, B_im, C_re, C_im);
    k_packW<<<(8 * 32 * 2048) / 256, 256>>>(W_out);
    k_matVS<<<(DMODEL * DSTATE + 127) / 128, 128>>>();
    k_matK<<<DMODEL, 64>>>();
    k_matW2K<<<(DMODEL * 4096 + 255) / 256, 256>>>();
    k_matW2V<<<(DMODEL * DSTATE + 127) / 128, 128>>>();
    k_zero<<<(BATCH * DMODEL + 255) / 256, 256>>>();
    k_scan_tc<<<BATCH * DMODEL, 128, SCAN_SMEM>>>(u, Dp);
    dim3 gg(8, (BATCH * LEN) / 128);
    k_gemm<<<gg, 256>>>(b_out);
    k_final<<<BATCH, 256>>>(W_dec, b_dec, out);
}

// round 16
// speedup vs baseline: 1.6190x; 1.0637x over previous
#include <cuda_runtime.h>
#include <math.h>

#define BATCH   16
#define DMODEL  512
#define DSTATE  64
#define LEN     4096

// ---------------- scratch (device globals: no allocations allowed) ----------
__device__ __align__(16) float g_zr[DMODEL*DSTATE];
__device__ __align__(16) float g_zi[DMODEL*DSTATE];
__device__ __align__(16) float g_wr[DMODEL*DSTATE];
__device__ __align__(16) float g_wi[DMODEL*DSTATE];
__device__ __align__(16) float g_zTr[DMODEL*DSTATE];   // z^64
__device__ __align__(16) float g_zTi[DMODEL*DSTATE];
__device__ __align__(16) float g_Kp[DMODEL*64];        // K'[lag] per d
__device__ __align__(16) float g_gelu[(size_t)BATCH*DMODEL*LEN];   // 128 MB
__device__ __align__(16) float g_pooled[BATCH*DMODEL];
// W_out pre-packed (tf32): [rblk8][kt32][h2][mf8][lane32][reg4]
__device__ __align__(16) unsigned int g_Wp[8*32*2048];
// scan stage-1 A: per d [mf8][kf8][lane32][reg4]; rows 0..63 Re z^s, 64..127 Im z^s
__device__ __align__(16) unsigned int g_VSp[(size_t)DMODEL*8192];
// scan stage-3 A: per d [mf4][kf24][lane32][reg4];
// cols 0..63 K'[t-s] Toeplitz, 64..127 Re z^{63-t}, 128..191 -Im z^{63-t}
__device__ __align__(16) unsigned int g_W2p[(size_t)DMODEL*12288];

__device__ __forceinline__ unsigned int f2tf32(float x) {
    unsigned int r;
    asm("cvt.rna.tf32.f32 %0, %1;" : "=r"(r) : "f"(x));
    return r;
}

// fragment slot helpers (match k_packW / k_gemm conventions, validated)
__device__ __forceinline__ int aidx(int row, int col, int kfN) {
    int mf = row >> 4, kf = col >> 3;
    int lane = (row & 7) * 4 + (col & 3);
    int reg  = ((row >> 3) & 1) + 2 * ((col >> 2) & 1);
    return (mf * kfN + kf) * 128 + lane * 4 + reg;
}
__device__ __forceinline__ int bidx(int k, int c) {   // B2: 24 kf x 8 nf
    int lane = (c & 7) * 4 + (k & 3);
    int reg  = (k >> 2) & 1;
    return (((k >> 3) * 8 + (c >> 3)) * 32 + lane) * 2 + reg;
}

// ---------------- kernel 1: SSM constants (fp64 for phase accuracy) ---------
__global__ void k_params(const float* __restrict__ log_dt,
                         const float* __restrict__ log_A_real,
                         const float* __restrict__ A_imag,
                         const float* __restrict__ B_re,
                         const float* __restrict__ B_im,
                         const float* __restrict__ C_re,
                         const float* __restrict__ C_im) {
    int i = blockIdx.x * blockDim.x + threadIdx.x;
    if (i >= DMODEL * DSTATE) return;
    int d = i / DSTATE;
    double dt   = exp((double)log_dt[d]);
    double Ar   = -exp((double)log_A_real[i]);
    double Ai   = (double)A_imag[i];
    double dtAr = Ar * dt, dtAi = Ai * dt;
    double er = exp(dtAr);
    double zr = er * cos(dtAi), zi = er * sin(dtAi);
    double den  = Ar * Ar + Ai * Ai;
    double numr = zr - 1.0, numi = zi;
    double qr = (numr * Ar + numi * Ai) / den;
    double qi = (numi * Ar - numr * Ai) / den;
    double Br = (double)B_re[i], Bi = (double)B_im[i];
    double bbr = qr * Br - qi * Bi, bbi = qr * Bi + qi * Br;
    double Cr = (double)C_re[i], Ci = (double)C_im[i];
    double wr = Cr * bbr - Ci * bbi, wi = Cr * bbi + Ci * bbr;
    double eT = exp(64.0 * dtAr);
    double phT = 64.0 * dtAi;
    g_zr[i] = (float)zr;   g_zi[i] = (float)zi;
    g_wr[i] = (float)wr;   g_wi[i] = (float)wi;
    g_zTr[i] = (float)(eT * cos(phT));
    g_zTi[i] = (float)(eT * sin(phT));
}

// ---------------- kernel 1b: pack W_out into tf32 mma fragment order --------
__global__ void k_packW(const float* __restrict__ W) {
    int flat = blockIdx.x * blockDim.x + threadIdx.x;   // 524288 total
    int reg  = flat & 3;
    int lane = (flat >> 2) & 31;
    int mf8  = (flat >> 7) & 7;
    int h    = (flat >> 10) & 1;
    int kt   = (flat >> 11) & 31;
    int rb   = flat >> 16;
    int m = mf8 * 16 + (lane >> 2) + 8 * (reg & 1);
    int k = kt * 16 + h * 8 + (lane & 3) + 4 * (reg >> 1);
    int wrow = (m < 64) ? rb * 64 + m : 448 + rb * 64 + m;
    g_Wp[flat] = f2tf32(W[wrow * 512 + k]);
}

// ---------------- scan-matrix builders --------------------------------------
// VS: row n -> Re z^s, row 64+n -> Im z^s (s = 0..63)
__global__ void k_matVS() {
    int id = blockIdx.x * blockDim.x + threadIdx.x;
    if (id >= DMODEL * DSTATE) return;
    int d = id >> 6, n = id & 63, dn = d * 64 + n;
    float zr = g_zr[dn], zi = g_zi[dn];
    unsigned int* base = g_VSp + (size_t)d * 8192;
    float vr = 1.0f, vi = 0.0f;
    for (int s = 0; s < 64; ++s) {
        base[aidx(n,      s, 8)] = f2tf32(vr);
        base[aidx(64 + n, s, 8)] = f2tf32(vi);
        float nr = vr * zr - vi * zi;
        vi = vr * zi + vi * zr; vr = nr;
    }
}

// K'[lag] = Re sum_n w_n z_n^{L-1-lag} = Re sum_n (w zT^63) z^{63-lag}
__global__ void k_matK() {   // <<<512, 64>>>
    __shared__ float sK[64 * 65];       // [lag][state]
    int d = blockIdx.x, n = threadIdx.x, dn = d * 64 + n;
    float zr = g_zr[dn], zi = g_zi[dn];
    float tr = g_zTr[dn], ti = g_zTi[dn];
    float cr = 1.0f, ci = 0.0f;
    int e = 63;                          // zT^63 by squaring
    while (e) {
        if (e & 1) { float nr = cr * tr - ci * ti; ci = cr * ti + ci * tr; cr = nr; }
        float nr2 = tr * tr - ti * ti; ti = 2.0f * tr * ti; tr = nr2;
        e >>= 1;
    }
    float wr = g_wr[dn], wi = g_wi[dn];
    float br = wr * cr - wi * ci, bi = wr * ci + wi * cr;
    for (int m = 0; m < 64; ++m) {       // value = w zT^63 z^m -> lag = 63-m
        sK[(63 - m) * 65 + n] = br;
        float nr = br * zr - bi * zi; bi = br * zi + bi * zr; br = nr;
    }
    __syncthreads();
    float s = 0.0f;
    for (int k2 = 0; k2 < 64; ++k2) s += sK[n * 65 + k2];
    g_Kp[d * 64 + n] = s;                // K'[lag = n]
}

// W2 cols 0..63: Kmat[t][s] = K'[t-s] (t>=s) else 0
__global__ void k_matW2K() {
    int id = blockIdx.x * blockDim.x + threadIdx.x;   // 512*4096
    if (id >= DMODEL * 4096) return;
    int d = id >> 12, t = (id >> 6) & 63, s = id & 63;
    float v = (t >= s) ? g_Kp[d * 64 + (t - s)] : 0.0f;
    g_W2p[(size_t)d * 12288 + aidx(t, s, 24)] = f2tf32(v);
}

// W2 cols 64+n: Re z^{63-t}; cols 128+n: -Im z^{63-t}
__global__ void k_matW2V() {
    int id = blockIdx.x * blockDim.x + threadIdx.x;
    if (id >= DMODEL * DSTATE) return;
    int d = id >> 6, n = id & 63, dn = d * 64 + n;
    float zr = g_zr[dn], zi = g_zi[dn];
    unsigned int* base = g_W2p + (size_t)d * 12288;
    float vr = 1.0f, vi = 0.0f;          // z^m, t = 63-m
    for (int m = 0; m < 64; ++m) {
        int t = 63 - m;
        base[aidx(t,  64 + n, 24)] = f2tf32(vr);
        base[aidx(t, 128 + n, 24)] = f2tf32(-vi);
        float nr = vr * zr - vi * zi;
        vi = vr * zi + vi * zr; vr = nr;
    }
}

// ---------------- kernel 2: zero pooled accumulator -------------------------
__global__ void k_zero() {
    int i = blockIdx.x * blockDim.x + threadIdx.x;
    if (i < BATCH * DMODEL) g_pooled[i] = 0.0f;
}

// ---------------- mma wrapper -----------------------------------------------
__device__ __forceinline__ void mma_tf32(float* c, const uint4 a, const uint2 b) {
    asm volatile(
        "mma.sync.aligned.m16n8k8.row.col.f32.tf32.tf32.f32 "
        "{%0,%1,%2,%3}, {%4,%5,%6,%7}, {%8,%9}, {%0,%1,%2,%3};"
        : "+f"(c[0]), "+f"(c[1]), "+f"(c[2]), "+f"(c[3])
        : "r"(a.x), "r"(a.y), "r"(a.z), "r"(a.w), "r"(b.x), "r"(b.y));
}

// ---------------- kernel 3: tensor-core chunked scan + skip + GELU ----------
// Block (128 thr) per (b,d).
// OVERLAY: sB2 kf>=8 region (uints 4096..12287) aliases sS (floats 0..8191 of
// the region at smemu+4096). S/P die exactly when G frags are written; the
// stage-2 rewrite buffers P into registers (2 threads per state) between
// barriers, so the overlay is race-free. Smem 81KB -> 49KB => 4 blocks/SM.
#define SCAN_SMEM (12544 * 4)

__global__ __launch_bounds__(128, 4) void k_scan_tc(const float* __restrict__ u,
                                                    const float* __restrict__ Dp) {
    extern __shared__ unsigned int smemu[];
    unsigned int* sB2 = smemu;                 // [U kf0..7 | G kf8..23 (overlaid)]
    float* sS = (float*)(smemu + 4096);        // S then P (128 x 66) — aliases G
    float* sY = sS;                            // y bounce (64 x 65), after G dead

    int tid = threadIdx.x, w = tid >> 5, lane = tid & 31;
    int bd = blockIdx.x, d = bd & (DMODEL - 1);
    const float* ub = u + (size_t)bd * LEN;
    float* gb = g_gelu + (size_t)bd * LEN;
    float Dd = Dp[d];

    // ---- stage 0: pack U into B fragments (k=s, n=c) ----
    #pragma unroll
    for (int i = 0; i < 32; ++i) {
        int x = tid + (i << 7);
        int s = x & 63, c = x >> 6;
        sB2[bidx(s, c)] = f2tf32(ub[x]);
    }
    __syncthreads();

    // ---- stage 1: S(128x64) = VS @ U ----
    {
        float acc[16][4];
        #pragma unroll
        for (int a = 0; a < 16; ++a)
            #pragma unroll
            for (int r = 0; r < 4; ++r) acc[a][r] = 0.0f;
        const uint4* Ab = (const uint4*)(g_VSp + (size_t)d * 8192);
        const uint2* Bb = (const uint2*)sB2;
        #pragma unroll
        for (int kf = 0; kf < 8; ++kf) {
            uint4 a0 = Ab[((2 * w)     * 8 + kf) * 32 + lane];
            uint4 a1 = Ab[((2 * w + 1) * 8 + kf) * 32 + lane];
            #pragma unroll
            for (int nf = 0; nf < 8; ++nf) {
                uint2 bf = Bb[(kf * 8 + nf) * 32 + lane];
                mma_tf32(acc[nf],     a0, bf);
                mma_tf32(acc[8 + nf], a1, bf);
            }
        }
        __syncthreads();   // U reads done before S overwrites nothing of U; G region free
        #pragma unroll
        for (int mi = 0; mi < 2; ++mi)
            #pragma unroll
            for (int nf = 0; nf < 8; ++nf)
                #pragma unroll
                for (int r = 0; r < 4; ++r) {
                    int row = 32 * w + 16 * mi + (lane >> 2) + 8 * (r >> 1);
                    int col = nf * 8 + 2 * (lane & 3) + (r & 1);
                    sS[row * 66 + col] = acc[mi * 8 + nf][r];
                }
    }
    __syncthreads();

    // ---- stage 2a: prefix P_c in place (threads 0..63, state n) ----
    int n2 = tid & 63, half = tid >> 6;
    int dn2 = d * 64 + n2;
    float zTr = g_zTr[dn2], zTi = g_zTi[dn2];
    float wr2 = g_wr[dn2],  wi2 = g_wi[dn2];
    if (tid < 64) {
        float* rR = sS + n2 * 66;
        float* rI = sS + (64 + n2) * 66;
        float Pr = 0.f, Pi = 0.f, dr = 1.f, di = 0.f;      // dc = zT^c
        for (int c = 0; c < 64; ++c) {
            float sr = rR[c], si = rI[c];
            rR[c] = Pr; rI[c] = Pi;                        // store P_c (sum c'<c)
            Pr += dr * sr - di * si;
            Pi += dr * si + di * sr;
            float ndr = dr * zTr - di * zTi;
            di = dr * zTi + di * zTr; dr = ndr;
        }
    }
    __syncthreads();

    // ---- stage 2b: buffer P into registers (2 threads/state, 32 c each) ----
    {
        int c0 = half * 32;
        float pR[32], pI[32];
        const float* rR = sS + n2 * 66;
        const float* rI = sS + (64 + n2) * 66;
        #pragma unroll
        for (int j = 0; j < 32; ++j) { pR[j] = rR[c0 + j]; pI[j] = rI[c0 + j]; }
        __syncthreads();                                   // all P buffered; G may clobber

        // e = w * zT^{63-c}; start at c = c0+31
        float er = wr2, ei = wi2;                          // half==1: 63-63=0 -> w
        if (half == 0) {                                   // need * zT^32
            float tr = zTr, ti = zTi;
            #pragma unroll
            for (int s = 0; s < 5; ++s) { float nr = tr * tr - ti * ti; ti = 2.0f * tr * ti; tr = nr; }
            float nr = er * tr - ei * ti; ei = er * ti + ei * tr; er = nr;
        }
        #pragma unroll
        for (int j = 31; j >= 0; --j) {
            int c = c0 + j;
            float Gr = er * pR[j] - ei * pI[j];
            float Gi = er * pI[j] + ei * pR[j];
            sB2[bidx(64 + n2, c)]  = f2tf32(Gr);
            sB2[bidx(128 + n2, c)] = f2tf32(Gi);
            float ner = er * zTr - ei * zTi;
            ei = er * zTi + ei * zTr; er = ner;
        }
    }
    __syncthreads();

    // ---- stage 3: y(64x64) = W2(64x192) @ [U; GR; GI] ----
    float acc2[8][4];
    #pragma unroll
    for (int a = 0; a < 8; ++a)
        #pragma unroll
        for (int r = 0; r < 4; ++r) acc2[a][r] = 0.0f;
    {
        const uint4* A2 = (const uint4*)(g_W2p + (size_t)d * 12288);
        const uint2* Bb = (const uint2*)sB2;
        #pragma unroll
        for (int kf = 0; kf < 24; ++kf) {
            uint4 a = A2[(w * 24 + kf) * 32 + lane];
            #pragma unroll
            for (int nf = 0; nf < 8; ++nf) {
                uint2 bf = Bb[(kf * 8 + nf) * 32 + lane];
                mma_tf32(acc2[nf], a, bf);
            }
        }
    }
    __syncthreads();                                        // G reads done before sY overlay
    // bounce y through smem for coalesced epilogue
    #pragma unroll
    for (int nf = 0; nf < 8; ++nf)
        #pragma unroll
        for (int r = 0; r < 4; ++r) {
            int t = 16 * w + (lane >> 2) + 8 * (r >> 1);
            int c = nf * 8 + 2 * (lane & 3) + (r & 1);
            sY[t * 65 + c] = acc2[nf][r];
        }
    __syncthreads();
    #pragma unroll
    for (int i = 0; i < 32; ++i) {
        int x = tid + (i << 7);
        int t = x & 63, c = x >> 6;
        float yv = fmaf(Dd, ub[x], sY[t * 65 + c]);
        float gv = 0.5f * yv * (1.0f + erff(yv * 0.7071067811865475f));
        gb[x] = gv;
    }
}

// ---------------- kernel 4: tf32 tensor-core GEMM + GLU + mean fused --------
#define SA_STRIDE 2048
#define SB_GRP    66
#define SB_STRIDE (32*SB_GRP)

__global__ __launch_bounds__(256) void k_gemm(const float* __restrict__ bout) {
    __shared__ __align__(16) float sh[8576];
    float* sA = sh;
    float* sB = sh + 2 * SA_STRIDE;

    int tid = threadIdx.x;
    int w = tid >> 5, lane = tid & 31;
    int wm = w & 1, wn = w >> 1;
    int rblk = blockIdx.x;
    int nblk = blockIdx.y;
    int col0 = nblk * 128;
    int b = col0 >> 12;
    const float* yg = g_gelu + (size_t)b * DMODEL * LEN + (col0 & (LEN - 1));
    const unsigned int* Wp = g_Wp + rblk * (32 * 2048);

    float acc[4][4][4];
    #pragma unroll
    for (int i = 0; i < 4; ++i)
        #pragma unroll
        for (int j = 0; j < 4; ++j)
            #pragma unroll
            for (int r = 0; r < 4; ++r) acc[i][j][r] = 0.0f;

    #pragma unroll
    for (int i = 0; i < 2; ++i) {
        int ia = tid + i * 256;
        uint4 va = *reinterpret_cast<const uint4*>(Wp + (size_t)ia * 4);
        *reinterpret_cast<uint4*>(reinterpret_cast<unsigned int*>(sA) + ia * 4) = va;
        int k = ia >> 5, n0 = (ia & 31) << 2;
        float4 vb = *reinterpret_cast<const float4*>(yg + (size_t)k * LEN + n0);
        float v[4] = {vb.x, vb.y, vb.z, vb.w};
        int h = k >> 3, kk = k & 3, reg = (k >> 2) & 1;
        #pragma unroll
        for (int e = 0; e < 4; ++e) {
            int nn = n0 + e;
            int l = ((nn & 7) << 2) | kk;
            sB[(h * 16 + (nn >> 3)) * SB_GRP + l * 2 + reg] = __uint_as_float(f2tf32(v[e]));
        }
    }
    __syncthreads();

    for (int kt = 0; kt < 32; ++kt) {
        int buf = kt & 1;
        bool has = kt < 31;
        uint4 pa[2]; float4 pb[2];
        if (has) {
            #pragma unroll
            for (int i = 0; i < 2; ++i) {
                int ia = tid + i * 256;
                pa[i] = *reinterpret_cast<const uint4*>(Wp + (size_t)(kt + 1) * 2048 + (size_t)ia * 4);
                int k = ia >> 5, n0 = (ia & 31) << 2;
                pb[i] = *reinterpret_cast<const float4*>(yg + (size_t)((kt + 1) * 16 + k) * LEN + n0);
            }
        }
        const float* sAb = sA + buf * SA_STRIDE;
        const float* sBb = sB + buf * SB_STRIDE;
        #pragma unroll
        for (int h = 0; h < 2; ++h) {
            uint4 af[4]; uint2 bf[4];
            #pragma unroll
            for (int mf = 0; mf < 4; ++mf)
                af[mf] = *reinterpret_cast<const uint4*>(sAb + ((h * 8 + wm * 4 + mf) * 128 + lane * 4));
            #pragma unroll
            for (int nf = 0; nf < 4; ++nf)
                bf[nf] = *reinterpret_cast<const uint2*>(sBb + (h * 16 + wn * 4 + nf) * SB_GRP + lane * 2);
            #pragma unroll
            for (int mf = 0; mf < 4; ++mf)
                #pragma unroll
                for (int nf = 0; nf < 4; ++nf)
                    mma_tf32(acc[mf][nf], af[mf], bf[nf]);
        }
        if (has) {
            int nb = buf ^ 1;
            #pragma unroll
            for (int i = 0; i < 2; ++i) {
                int ia = tid + i * 256;
                *reinterpret_cast<uint4*>(reinterpret_cast<unsigned int*>(sA + nb * SA_STRIDE) + ia * 4) = pa[i];
                int k = ia >> 5, n0 = (ia & 31) << 2;
                float v[4] = {pb[i].x, pb[i].y, pb[i].z, pb[i].w};
                int h = k >> 3, kk = k & 3, reg = (k >> 2) & 1;
                float* sBn = sB + nb * SB_STRIDE;
                #pragma unroll
                for (int e = 0; e < 4; ++e) {
                    int nn = n0 + e;
                    int l = ((nn & 7) << 2) | kk;
                    sBn[(h * 16 + (nn >> 3)) * SB_GRP + l * 2 + reg] = __uint_as_float(f2tf32(v[e]));
                }
            }
        }
        __syncthreads();
    }

    float* Sg  = sh;
    float* red = sh + 64 * 129;

    if (wm == 1) {
        #pragma unroll
        for (int mf = 0; mf < 4; ++mf)
            #pragma unroll
            for (int hi = 0; hi < 2; ++hi) {
                int row = mf * 16 + (lane >> 2) + 8 * hi;
                float bo = bout[512 + rblk * 64 + row];
                #pragma unroll
                for (int nf = 0; nf < 4; ++nf)
                    #pragma unroll
                    for (int c01 = 0; c01 < 2; ++c01) {
                        int col = wn * 32 + nf * 8 + ((lane & 3) << 1) + c01;
                        float gv = acc[mf][nf][2 * hi + c01] + bo;
                        Sg[row * 129 + col] = 1.0f / (1.0f + expf(-gv));
                    }
            }
    }
    __syncthreads();
    if (wm == 0) {
        #pragma unroll
        for (int mf = 0; mf < 4; ++mf)
            #pragma unroll
            for (int hi = 0; hi < 2; ++hi) {
                int row = mf * 16 + (lane >> 2) + 8 * hi;
                float bo = bout[rblk * 64 + row];
                float rs = 0.0f;
                #pragma unroll
                for (int nf = 0; nf < 4; ++nf)
                    #pragma unroll
                    for (int c01 = 0; c01 < 2; ++c01) {
                        int col = wn * 32 + nf * 8 + ((lane & 3) << 1) + c01;
                        rs += (acc[mf][nf][2 * hi + c01] + bo) * Sg[row * 129 + col];
                    }
                rs += __shfl_xor_sync(0xffffffffu, rs, 1);
                rs += __shfl_xor_sync(0xffffffffu, rs, 2);
                if ((lane & 3) == 0) red[row * 4 + wn] = rs;
            }
    }
    __syncthreads();
    if (tid < 64) {
        float s = red[tid * 4] + red[tid * 4 + 1] + red[tid * 4 + 2] + red[tid * 4 + 3];
        atomicAdd(&g_pooled[b * DMODEL + rblk * 64 + tid], s);
    }
}

// ---------------- kernel 5: mean scale + decoder ----------------------------
__global__ void k_final(const float* __restrict__ Wd,
                        const float* __restrict__ bd,
                        float* __restrict__ out) {
    int b = blockIdx.x;
    __shared__ float r[256];
    float s = 0.0f;
    for (int c = threadIdx.x; c < DMODEL; c += 256)
        s += Wd[c] * g_pooled[b * DMODEL + c];
    r[threadIdx.x] = s;
    __syncthreads();
    for (int st = 128; st > 0; st >>= 1) {
        if (threadIdx.x < st) r[threadIdx.x] += r[threadIdx.x + st];
        __syncthreads();
    }
    if (threadIdx.x == 0) out[b] = r[0] * (1.0f / (float)LEN) + bd[0];
}

// ---------------- launch -----------------------------------------------------
extern "C" void kernel_launch(void* const* d_in, const int* in_sizes, int n_in,
                              void* d_out, int out_size) {
    const float* u          = (const float*)d_in[0];
    const float* log_dt     = (const float*)d_in[1];
    const float* log_A_real = (const float*)d_in[2];
    const float* A_imag     = (const float*)d_in[3];
    const float* B_re       = (const float*)d_in[4];
    const float* B_im       = (const float*)d_in[5];
    const float* C_re       = (const float*)d_in[6];
    const float* C_im       = (const float*)d_in[7];
    const float* Dp         = (const float*)d_in[8];
    const float* W_out      = (const float*)d_in[9];
    const float* b_out      = (const float*)d_in[10];
    const float* W_dec      = (const float*)d_in[11];
    const float* b_dec      = (const float*)d_in[12];
    float* out = (float*)d_out;

    cudaFuncSetAttribute(k_scan_tc, cudaFuncAttributeMaxDynamicSharedMemorySize,
                         SCAN_SMEM);

    k_params<<<(DMODEL * DSTATE + 127) / 128, 128>>>(log_dt, log_A_real, A_imag,
                                                     B_re, B_im, C_re, C_im);
    k_packW<<<(8 * 32 * 2048) / 256, 256>>>(W_out);
    k_matVS<<<(DMODEL * DSTATE + 127) / 128, 128>>>();
    k_matK<<<DMODEL, 64>>>();
    k_matW2K<<<(DMODEL * 4096 + 255) / 256, 256>>>();
    k_matW2V<<<(DMODEL * DSTATE + 127) / 128, 128>>>();
    k_zero<<<(BATCH * DMODEL + 255) / 256, 256>>>();
    k_scan_tc<<<BATCH * DMODEL, 128, SCAN_SMEM>>>(u, Dp);
    dim3 gg(8, (BATCH * LEN) / 128);
    k_gemm<<<gg, 256>>>(b_out);
    k_final<<<BATCH, 256>>>(W_dec, b_dec, out);
}